// round 16
// baseline (speedup 1.0000x reference)
#include <cuda_runtime.h>
#include <cuda_fp16.h>
#include <cstdint>

// ---------------------------------------------------------------------------
// Char-LSTM via mma.sync (HMMA fp16 hi/lo split). BATCH=512, UNITS=256, SEQ=1024.
//
// 32 clusters x 4 CTAs (grid=128), 512 thr/CTA, 1 CTA/SM.
//   cluster -> 16 batches; CTA rank r -> 64 units = 256 gate cols.
//   warp w (0..15) -> units 4w..4w+3 (2 n8-tiles, col = gate*2 + unit).
// W_hi B-frags register-resident; W_lo in SMEM via ldmatrix (x2 pairs).
// gates = Ahi*Whi + (Alo*Whi + Ahi*Wlo)/64  (A = h fp16 hi/lo, lo scaled x64).
// Cell in registers after a 4-shuffle quad transpose; h hi/lo broadcast to
// 3 peer CTAs via st.shared::cluster.v2 (own slice via local STS);
// one barrier.cluster per step. Wx cp.async-staged one step ahead.
// NEW vs best: split-K "own-chunk first" — register slot kt maps to global
// k-tile (4*rank+kt)%16, so each step runs 4 own k-tiles (local h) BEFORE
// cluster_wait, hiding broadcast flight + barrier skew under real gemm work.
// ---------------------------------------------------------------------------

namespace {
constexpr int kSeq     = 1024;
constexpr int kThreads = 512;
constexpr float kScale = 64.0f;
constexpr float kInv   = 1.0f / 64.0f;

// SMEM map
constexpr uint32_t WLO      = 0;                     // W_lo [256 n][k] 528B rows
constexpr uint32_t WLO_SIZE = 256u * 528u;           // 135168
constexpr uint32_t ABASE    = WLO_SIZE;              // h staging, 2 bufs x (hi+lo)
constexpr uint32_t A_ROW    = 528;
constexpr uint32_t A_ARR    = 16u * A_ROW;           // 8448
constexpr uint32_t A_BUF    = 2u * A_ARR;            // 16896 (hi then lo)
constexpr uint32_t WXS      = ABASE + 2u * A_BUF;    // 168960: Wx staging
constexpr uint32_t WXS_ROW  = 1040;                  // 260 floats per batch (pad)
constexpr uint32_t WXS_BUF  = 16u * WXS_ROW;         // 16640
constexpr uint32_t TKS      = WXS + 2u * WXS_BUF;    // 202240: 2 x 16 tokens
constexpr uint32_t SMEM_BYTES = TKS + 128;           // 202368
}  // namespace

// ---------------- PTX helpers ----------------------------------------------
__device__ __forceinline__ uint32_t smem_u32(const void* p) {
    uint32_t a;
    asm("{ .reg .u64 t; cvta.to.shared.u64 t, %1; cvt.u32.u64 %0, t; }" : "=r"(a) : "l"(p));
    return a;
}
__device__ __forceinline__ uint32_t mapa_u32(uint32_t a, uint32_t r) {
    uint32_t o;
    asm("mapa.shared::cluster.u32 %0, %1, %2;" : "=r"(o) : "r"(a), "r"(r));
    return o;
}
__device__ __forceinline__ void st_cluster_v2(uint32_t a, uint32_t v0, uint32_t v1) {
    asm volatile("st.shared::cluster.v2.b32 [%0], {%1, %2};"
                 :: "r"(a), "r"(v0), "r"(v1) : "memory");
}
__device__ __forceinline__ void st_local_v2(uint32_t a, uint32_t v0, uint32_t v1) {
    asm volatile("st.shared.v2.b32 [%0], {%1, %2};"
                 :: "r"(a), "r"(v0), "r"(v1) : "memory");
}
__device__ __forceinline__ void cluster_arrive_() {
    asm volatile("barrier.cluster.arrive.aligned;" ::: "memory");
}
__device__ __forceinline__ void cluster_wait_() {
    asm volatile("barrier.cluster.wait.aligned;" ::: "memory");
}
__device__ __forceinline__ uint32_t cta_rank_() {
    uint32_t r; asm("mov.u32 %0, %%cluster_ctarank;" : "=r"(r)); return r;
}
__device__ __forceinline__ void cp16_(uint32_t dst, const void* src) {
    asm volatile("cp.async.cg.shared.global [%0], [%1], 16;"
                 :: "r"(dst), "l"(src) : "memory");
}
__device__ __forceinline__ void cp4_(uint32_t dst, const void* src) {
    asm volatile("cp.async.ca.shared.global [%0], [%1], 4;"
                 :: "r"(dst), "l"(src) : "memory");
}
__device__ __forceinline__ void cp_commit_() {
    asm volatile("cp.async.commit_group;" ::: "memory");
}
__device__ __forceinline__ void cp_wait0_() {
    asm volatile("cp.async.wait_group 0;" ::: "memory");
}
__device__ __forceinline__ void ldsm_x4_(uint32_t* r, uint32_t addr) {
    asm volatile("ldmatrix.sync.aligned.m8n8.x4.shared.b16 {%0,%1,%2,%3}, [%4];"
                 : "=r"(r[0]), "=r"(r[1]), "=r"(r[2]), "=r"(r[3]) : "r"(addr));
}
__device__ __forceinline__ void ldsm_x2_(uint32_t* r, uint32_t addr) {
    asm volatile("ldmatrix.sync.aligned.m8n8.x2.shared.b16 {%0,%1}, [%2];"
                 : "=r"(r[0]), "=r"(r[1]) : "r"(addr));
}
__device__ __forceinline__ void mma16816_(float* d, const uint32_t* a,
                                          uint32_t b0, uint32_t b1) {
    asm volatile(
        "mma.sync.aligned.m16n8k16.row.col.f32.f16.f16.f32 "
        "{%0,%1,%2,%3}, {%4,%5,%6,%7}, {%8,%9}, {%0,%1,%2,%3};"
        : "+f"(d[0]), "+f"(d[1]), "+f"(d[2]), "+f"(d[3])
        : "r"(a[0]), "r"(a[1]), "r"(a[2]), "r"(a[3]), "r"(b0), "r"(b1));
}
__device__ __forceinline__ float sigf(float x) {
    return __fdividef(1.0f, 1.0f + __expf(-x));
}
__device__ __forceinline__ float tanhf_(float x) { return 2.0f * sigf(2.0f * x) - 1.0f; }
__device__ __forceinline__ uint32_t pack2h(float a, float b) {
    __half2 h = __floats2half2_rn(a, b);
    return *reinterpret_cast<uint32_t*>(&h);
}
// 4x4 transpose within a quad.
__device__ __forceinline__ void quad_transpose(float g[4], int m) {
    float s0 = (m & 1) ? g[0] : g[1];
    float s1 = (m & 1) ? g[2] : g[3];
    s0 = __shfl_xor_sync(0xffffffffu, s0, 1);
    s1 = __shfl_xor_sync(0xffffffffu, s1, 1);
    if (m & 1) { g[0] = s0; g[2] = s1; } else { g[1] = s0; g[3] = s1; }
    float t0 = (m & 2) ? g[0] : g[2];
    float t1 = (m & 2) ? g[1] : g[3];
    t0 = __shfl_xor_sync(0xffffffffu, t0, 2);
    t1 = __shfl_xor_sync(0xffffffffu, t1, 2);
    if (m & 2) { g[0] = t0; g[1] = t1; } else { g[2] = t0; g[3] = t1; }
}

extern __shared__ char smem_raw[];

__global__ __launch_bounds__(kThreads, 1) __cluster_dims__(4, 1, 1)
void lstm_splitk_kernel(const int*   __restrict__ tokens,  // [512,1024]
                        const float* __restrict__ Wx,      // [128,1024]
                        const float* __restrict__ Wh,      // [256,1024]
                        const float* __restrict__ bias,    // [1024]
                        const float* __restrict__ Wd,      // [256,128]
                        const float* __restrict__ bd,      // [128]
                        float*       __restrict__ out)     // [512,128]
{
    const int tid  = threadIdx.x;
    const int lane = tid & 31;
    const int w    = tid >> 5;
    const int m    = lane & 3;
    const int p    = m & 1;
    const int r    = (lane >> 2) + 8 * (m >> 1);
    const uint32_t rank = cta_rank_();
    const int bbase = (blockIdx.x >> 2) * 16;
    const uint32_t sbase = smem_u32(smem_raw);

    // ---- zero A staging (both buffers) ------------------------------------
    for (uint32_t i = tid; i < (2u * A_BUF) / 16u; i += kThreads)
        reinterpret_cast<uint4*>(smem_raw + ABASE)[i] = make_uint4(0, 0, 0, 0);

    // ---- W_lo into SMEM (global k order) -----------------------------------
    for (int idx = tid; idx < 256 * 256; idx += kThreads) {
        int n = idx >> 8, k = idx & 255;
        int gate = (n & 7) >> 1;
        int ul = 4 * (n >> 4) + 2 * ((n >> 3) & 1) + (n & 1);
        float v = Wh[k * 1024 + gate * 256 + (int)rank * 64 + ul];
        float h = __half2float(__float2half_rn(v));
        *reinterpret_cast<__half*>(smem_raw + WLO + n * 528 + k * 2) =
            __float2half_rn((v - h) * kScale);
    }

    // ---- W_hi B-fragments, register-resident --------------------------------
    // Register slot kt holds GLOBAL k-tile g = (kt + 4*rank) & 15, so slots
    // 0..3 are this CTA's own k-chunk (locally produced h).
    uint32_t wh0[32], wh1[32];
#pragma unroll
    for (int j = 0; j < 2; ++j) {
        int cc = lane >> 2;
        int ul = 4 * w + 2 * j + (cc & 1);
        int gc = (cc >> 1) * 256 + (int)rank * 64 + ul;
#pragma unroll
        for (int kt = 0; kt < 16; ++kt) {
            int g  = (kt + 4 * (int)rank) & 15;
            int k0 = g * 16 + (lane & 3) * 2;
#pragma unroll
            for (int jj = 0; jj < 2; ++jj) {
                float a = Wh[(k0 + 8 * jj) * 1024 + gc];
                float b = Wh[(k0 + 8 * jj + 1) * 1024 + gc];
                uint32_t v = pack2h(__half2float(__float2half_rn(a)),
                                    __half2float(__float2half_rn(b)));
                if (j == 0) wh0[kt * 2 + jj] = v; else wh1[kt * 2 + jj] = v;
            }
        }
    }

    // ---- per-lane cell constants ------------------------------------------
    float bi[2][4];
#pragma unroll
    for (int j = 0; j < 2; ++j)
#pragma unroll
        for (int g = 0; g < 4; ++g)
            bi[j][g] = bias[g * 256 + (int)rank * 64 + 4 * w + 2 * j + p];
    float cst[2] = {0.f, 0.f};

    // ldmatrix lane address offsets
    const uint32_t aoff =
        (uint32_t)(((((lane >> 3) & 1) * 8) + (lane & 7)) * 528 +
                   ((lane >> 4) & 1) * 16);
    const uint32_t bloff0 = sbase + WLO +
        (uint32_t)((w * 16 + (lane & 7)) * 528 + ((lane >> 3) & 1) * 16);
    const uint32_t bloff1 = bloff0 + 8u * 528u;
    const uint32_t kbase = (uint32_t)(4 * (int)rank) * 32u;  // own-chunk byte off

    // peer DSMEM bases for the 3 other ranks
    uint32_t peerx[3];
    {
        int idx = 0;
#pragma unroll
        for (int pr = 0; pr < 4; ++pr)
            if ((uint32_t)pr != rank) peerx[idx++] = mapa_u32(sbase, (uint32_t)pr);
    }

    // ---- prologue: stage Wx(t=0) + tokens(t=1) synchronously ---------------
#pragma unroll
    for (int cc = 0; cc < 2; ++cc) {
        int cidx = tid + cc * 512;
        int b = cidx >> 6, c = (cidx & 63) * 4;
        int tok0 = tokens[(bbase + b) * kSeq];
        float4 v = *reinterpret_cast<const float4*>(
            Wx + tok0 * 1024 + (c >> 6) * 256 + (int)rank * 64 + (c & 63));
        *reinterpret_cast<float4*>(smem_raw + WXS + (uint32_t)(b * 1040 + c * 4)) = v;
    }
    if (tid < 16)
        reinterpret_cast<int*>(smem_raw + TKS)[tid] =
            tokens[(bbase + tid) * kSeq + 1];

    __syncthreads();
    cluster_arrive_();
    cluster_wait_();

    for (int t = 0; t < kSeq; ++t) {
        const uint32_t q = (uint32_t)(t & 1);
        const uint32_t ahB = sbase + ABASE + q * A_BUF + aoff;
        const uint32_t alB = ahB + A_ARR;

        float aA0[4] = {0, 0, 0, 0}, aB0[4] = {0, 0, 0, 0};
        float aA1[4] = {0, 0, 0, 0}, aB1[4] = {0, 0, 0, 0};

        // ---- pass 1: own 4 k-tiles (local h, no barrier needed) ------------
#pragma unroll
        for (int kt = 0; kt < 4; ++kt) {
            const uint32_t ko = (kbase + (uint32_t)(kt * 32)) & 511u;
            uint32_t ah[4], al[4], b0[2], b1[2];
            ldsm_x4_(ah, ahB + ko);
            ldsm_x4_(al, alB + ko);
            ldsm_x2_(b0, bloff0 + ko);
            ldsm_x2_(b1, bloff1 + ko);
            mma16816_(aA0, ah, wh0[2 * kt], wh0[2 * kt + 1]);
            mma16816_(aB0, al, wh0[2 * kt], wh0[2 * kt + 1]);
            mma16816_(aB0, ah, b0[0], b0[1]);
            mma16816_(aA1, ah, wh1[2 * kt], wh1[2 * kt + 1]);
            mma16816_(aB1, al, wh1[2 * kt], wh1[2 * kt + 1]);
            mma16816_(aB1, ah, b1[0], b1[1]);
        }

        // ---- remote h(t-1) now needed: wait (flight/skew already hidden) ---
        cluster_wait_();
        cp_wait0_();   // staged groups are a full iteration old -> free

        // ---- cp.async stage: Wx(t+1) via tokens staged last step -----------
        {
            const int* tksP =
                reinterpret_cast<const int*>(smem_raw + TKS) + (int)(q * 16);
            uint32_t wdst = sbase + WXS + (q ^ 1u) * WXS_BUF;
#pragma unroll
            for (int cc = 0; cc < 2; ++cc) {
                int cidx = tid + cc * 512;
                int b = cidx >> 6, c = (cidx & 63) * 4;
                int tok1 = tksP[b];
                cp16_(wdst + (uint32_t)(b * 1040 + c * 4),
                      Wx + tok1 * 1024 + (c >> 6) * 256 + (int)rank * 64 + (c & 63));
            }
            if (tid < 16) {
                int t2 = (t + 2 < kSeq) ? t + 2 : kSeq - 1;
                cp4_(sbase + TKS + ((q ^ 1u) * 16u + (uint32_t)tid) * 4u,
                     tokens + (bbase + tid) * kSeq + t2);
            }
            cp_commit_();
        }

        // ---- pass 2: remaining 12 k-tiles ----------------------------------
#pragma unroll
        for (int kt = 4; kt < 16; ++kt) {
            const uint32_t ko = (kbase + (uint32_t)(kt * 32)) & 511u;
            uint32_t ah[4], al[4], b0[2], b1[2];
            ldsm_x4_(ah, ahB + ko);
            ldsm_x4_(al, alB + ko);
            ldsm_x2_(b0, bloff0 + ko);
            ldsm_x2_(b1, bloff1 + ko);
            mma16816_(aA0, ah, wh0[2 * kt], wh0[2 * kt + 1]);
            mma16816_(aB0, al, wh0[2 * kt], wh0[2 * kt + 1]);
            mma16816_(aB0, ah, b0[0], b0[1]);
            mma16816_(aA1, ah, wh1[2 * kt], wh1[2 * kt + 1]);
            mma16816_(aB1, al, wh1[2 * kt], wh1[2 * kt + 1]);
            mma16816_(aB1, ah, b1[0], b1[1]);
        }

        // ---- combine, quad-transpose, cell (wx from staged SMEM) -----------
        const float* wxr = reinterpret_cast<const float*>(smem_raw + WXS + q * WXS_BUF)
                           + r * 260;
        float hv[2];
#pragma unroll
        for (int j = 0; j < 2; ++j) {
            float g[4];
#pragma unroll
            for (int k = 0; k < 4; ++k)
                g[k] = j ? fmaf(aB1[k], kInv, aA1[k]) : fmaf(aB0[k], kInv, aA0[k]);
            quad_transpose(g, m);
            int ul = 4 * w + 2 * j + p;
            float gi = g[0] + wxr[        ul] + bi[j][0];
            float gj = g[1] + wxr[ 64 +   ul] + bi[j][1];
            float gf = g[2] + wxr[128 +   ul] + bi[j][2];
            float go = g[3] + wxr[192 +   ul] + bi[j][3];
            cst[j] = cst[j] * sigf(gf + 1.0f) + sigf(gi) * tanhf_(gj);
            hv[j] = tanhf_(cst[j]) * sigf(go);
        }

        // ---- pack unit-pairs; own slice local STS, 3 peers via DSMEM -------
        {
            float hp0 = __shfl_xor_sync(0xffffffffu, hv[0], 1);
            float hp1 = __shfl_xor_sync(0xffffffffu, hv[1], 1);
            uint32_t v0, v1;
            if (p == 0) {            // even lanes carry hi halves
                v0 = pack2h(hv[0], hp0);
                v1 = pack2h(hv[1], hp1);
            } else {                 // odd lanes carry scaled-lo halves
                float e0 = hp0 - __half2float(__float2half_rn(hp0));
                float o0 = hv[0] - __half2float(__float2half_rn(hv[0]));
                float e1 = hp1 - __half2float(__float2half_rn(hp1));
                float o1 = hv[1] - __half2float(__float2half_rn(hv[1]));
                v0 = pack2h(e0 * kScale, o0 * kScale);
                v1 = pack2h(e1 * kScale, o1 * kScale);
            }
            uint32_t off = ABASE + (q ^ 1u) * A_BUF + (p ? A_ARR : 0u) +
                           (uint32_t)(r * 528 + (int)rank * 128 + 8 * w);
            st_local_v2(sbase + off, v0, v1);
#pragma unroll
            for (int pr = 0; pr < 3; ++pr)
                st_cluster_v2(peerx[pr] + off, v0, v1);
        }

        __syncthreads();     // own h(t) slice visible CTA-wide for pass 1
        cluster_arrive_();
    }

    cluster_wait_();         // final arrivals: remote h slices delivered

    // ---- dense epilogue: out[b,:] = h @ Wd + bd ---------------------------
    {
        float* wds = reinterpret_cast<float*>(smem_raw + WLO);   // 32KB staging
        for (int idx = tid; idx < 256 * 32; idx += kThreads)
            wds[idx] = Wd[(idx >> 5) * 128 + (int)rank * 32 + (idx & 31)];
        __syncthreads();

        int ci = tid & 31, b = tid >> 5;
        int col = (int)rank * 32 + ci;
        const __half* hh = reinterpret_cast<const __half*>(
            smem_raw + ABASE + (uint32_t)(b * 528));
        const __half* hl = reinterpret_cast<const __half*>(
            smem_raw + ABASE + A_ARR + (uint32_t)(b * 528));
        float acc = bd[col];
#pragma unroll 8
        for (int u = 0; u < 256; ++u) {
            float h = __half2float(hh[u]) + __half2float(hl[u]) * kInv;
            acc += h * wds[u * 32 + ci];
        }
        out[(bbase + b) * 128 + col] = acc;
    }
    cluster_arrive_(); cluster_wait_();
}

extern "C" void kernel_launch(void* const* d_in, const int* in_sizes, int n_in,
                              void* d_out, int out_size) {
    (void)in_sizes; (void)n_in; (void)out_size;
    const int*   tokens = (const int*)d_in[0];
    const float* Wx     = (const float*)d_in[1];
    const float* Wh     = (const float*)d_in[2];
    const float* b      = (const float*)d_in[3];
    const float* Wd     = (const float*)d_in[4];
    const float* bd     = (const float*)d_in[5];
    float* out = (float*)d_out;

    cudaFuncSetAttribute(lstm_splitk_kernel,
                         cudaFuncAttributeMaxDynamicSharedMemorySize,
                         (int)SMEM_BYTES);
    // 32 clusters of 4 CTAs (static __cluster_dims__), 1 CTA/SM.
    lstm_splitk_kernel<<<128, kThreads, SMEM_BYTES>>>(tokens, Wx, Wh, b, Wd, bd, out);
}

// round 17
// speedup vs baseline: 1.4121x; 1.4121x over previous
#include <cuda_runtime.h>
#include <cuda_fp16.h>
#include <cstdint>

// ---------------------------------------------------------------------------
// Char-LSTM via mma.sync (HMMA). BATCH=512, UNITS=256, SEQ=1024.
//
// 32 clusters x 4 CTAs (grid=128), 512 thr/CTA, 1 CTA/SM.
//   cluster -> 16 batches; CTA rank r -> 64 units = 256 gate cols.
//   warp w (0..15) -> units 4w..4w+3 (2 n8-tiles, col = gate*2 + unit).
// Precision (measured safe in R9/R13: rel_err 2.2e-4 < 1e-3):
//   gates = A_hi*W_hi + A_hi*W_lo/64. W fp16 hi/lo (systematic error
//   corrected); h stored fp16 (rounding = fresh per-step noise, contracts).
// W_hi B-frags register-resident; W_lo in SMEM via one ldmatrix.x4/kt.
// NEW vs best: 2-term gemm with EXPLICIT register double-buffering of
// fragments (load kt+1 while kt's 4 independent MMA chains issue) --
// restores the ILP that R9's naive 2-term lost. SMEM gemm traffic
// 384->256 KB/step; HMMA 96->64/warp; h staging/broadcast hi-only.
// Cell in registers after quad transpose; h broadcast to 4 cluster CTAs
// via st.shared::cluster.v2 (p=0 lanes); one barrier.cluster per step.
// Wx cp.async-staged one step ahead (R10 win, kept byte-identical).
// ---------------------------------------------------------------------------

namespace {
constexpr int kSeq     = 1024;
constexpr int kThreads = 512;
constexpr float kScale = 64.0f;
constexpr float kInv   = 1.0f / 64.0f;

// SMEM map
constexpr uint32_t WLO      = 0;                     // W_lo [256 n][k] 528B rows
constexpr uint32_t WLO_SIZE = 256u * 528u;           // 135168
constexpr uint32_t ABASE    = WLO_SIZE;              // h staging, 2 bufs (hi only)
constexpr uint32_t A_ROW    = 528;
constexpr uint32_t A_ARR    = 16u * A_ROW;           // 8448 per buffer
constexpr uint32_t WXS      = ABASE + 2u * A_ARR;    // 152064: Wx staging
constexpr uint32_t WXS_ROW  = 1040;                  // 260 floats per batch (pad)
constexpr uint32_t WXS_BUF  = 16u * WXS_ROW;         // 16640
constexpr uint32_t TKS      = WXS + 2u * WXS_BUF;    // 185344: 2 x 16 tokens
constexpr uint32_t SMEM_BYTES = TKS + 128;           // 185472
}  // namespace

// ---------------- PTX helpers ----------------------------------------------
__device__ __forceinline__ uint32_t smem_u32(const void* p) {
    uint32_t a;
    asm("{ .reg .u64 t; cvta.to.shared.u64 t, %1; cvt.u32.u64 %0, t; }" : "=r"(a) : "l"(p));
    return a;
}
__device__ __forceinline__ uint32_t mapa_u32(uint32_t a, uint32_t r) {
    uint32_t o;
    asm("mapa.shared::cluster.u32 %0, %1, %2;" : "=r"(o) : "r"(a), "r"(r));
    return o;
}
__device__ __forceinline__ void st_cluster_v2(uint32_t a, uint32_t v0, uint32_t v1) {
    asm volatile("st.shared::cluster.v2.b32 [%0], {%1, %2};"
                 :: "r"(a), "r"(v0), "r"(v1) : "memory");
}
__device__ __forceinline__ void cluster_arrive_() {
    asm volatile("barrier.cluster.arrive.aligned;" ::: "memory");
}
__device__ __forceinline__ void cluster_wait_() {
    asm volatile("barrier.cluster.wait.aligned;" ::: "memory");
}
__device__ __forceinline__ uint32_t cta_rank_() {
    uint32_t r; asm("mov.u32 %0, %%cluster_ctarank;" : "=r"(r)); return r;
}
__device__ __forceinline__ void cp16_(uint32_t dst, const void* src) {
    asm volatile("cp.async.cg.shared.global [%0], [%1], 16;"
                 :: "r"(dst), "l"(src) : "memory");
}
__device__ __forceinline__ void cp4_(uint32_t dst, const void* src) {
    asm volatile("cp.async.ca.shared.global [%0], [%1], 4;"
                 :: "r"(dst), "l"(src) : "memory");
}
__device__ __forceinline__ void cp_commit_() {
    asm volatile("cp.async.commit_group;" ::: "memory");
}
__device__ __forceinline__ void cp_wait0_() {
    asm volatile("cp.async.wait_group 0;" ::: "memory");
}
__device__ __forceinline__ void ldsm_x4_(uint32_t* r, uint32_t addr) {
    asm volatile("ldmatrix.sync.aligned.m8n8.x4.shared.b16 {%0,%1,%2,%3}, [%4];"
                 : "=r"(r[0]), "=r"(r[1]), "=r"(r[2]), "=r"(r[3]) : "r"(addr));
}
__device__ __forceinline__ void mma16816_(float* d, const uint32_t* a,
                                          uint32_t b0, uint32_t b1) {
    asm volatile(
        "mma.sync.aligned.m16n8k16.row.col.f32.f16.f16.f32 "
        "{%0,%1,%2,%3}, {%4,%5,%6,%7}, {%8,%9}, {%0,%1,%2,%3};"
        : "+f"(d[0]), "+f"(d[1]), "+f"(d[2]), "+f"(d[3])
        : "r"(a[0]), "r"(a[1]), "r"(a[2]), "r"(a[3]), "r"(b0), "r"(b1));
}
__device__ __forceinline__ float sigf(float x) {
    return __fdividef(1.0f, 1.0f + __expf(-x));
}
__device__ __forceinline__ float tanhf_(float x) { return 2.0f * sigf(2.0f * x) - 1.0f; }
__device__ __forceinline__ uint32_t pack2h(float a, float b) {
    __half2 h = __floats2half2_rn(a, b);
    return *reinterpret_cast<uint32_t*>(&h);
}
// 4x4 transpose within a quad.
__device__ __forceinline__ void quad_transpose(float g[4], int m) {
    float s0 = (m & 1) ? g[0] : g[1];
    float s1 = (m & 1) ? g[2] : g[3];
    s0 = __shfl_xor_sync(0xffffffffu, s0, 1);
    s1 = __shfl_xor_sync(0xffffffffu, s1, 1);
    if (m & 1) { g[0] = s0; g[2] = s1; } else { g[1] = s0; g[3] = s1; }
    float t0 = (m & 2) ? g[0] : g[2];
    float t1 = (m & 2) ? g[1] : g[3];
    t0 = __shfl_xor_sync(0xffffffffu, t0, 2);
    t1 = __shfl_xor_sync(0xffffffffu, t1, 2);
    if (m & 2) { g[0] = t0; g[1] = t1; } else { g[2] = t0; g[3] = t1; }
}

extern __shared__ char smem_raw[];

__global__ __launch_bounds__(kThreads, 1) __cluster_dims__(4, 1, 1)
void lstm_db_kernel(const int*   __restrict__ tokens,  // [512,1024]
                    const float* __restrict__ Wx,      // [128,1024]
                    const float* __restrict__ Wh,      // [256,1024]
                    const float* __restrict__ bias,    // [1024]
                    const float* __restrict__ Wd,      // [256,128]
                    const float* __restrict__ bd,      // [128]
                    float*       __restrict__ out)     // [512,128]
{
    const int tid  = threadIdx.x;
    const int lane = tid & 31;
    const int w    = tid >> 5;
    const int m    = lane & 3;
    const int p    = m & 1;
    const int r    = (lane >> 2) + 8 * (m >> 1);
    const uint32_t rank = cta_rank_();
    const int bbase = (blockIdx.x >> 2) * 16;
    const uint32_t sbase = smem_u32(smem_raw);

    // ---- zero A staging (both buffers) ------------------------------------
    for (uint32_t i = tid; i < (2u * A_ARR) / 16u; i += kThreads)
        reinterpret_cast<uint4*>(smem_raw + ABASE)[i] = make_uint4(0, 0, 0, 0);

    // ---- W_lo into SMEM ----------------------------------------------------
    for (int idx = tid; idx < 256 * 256; idx += kThreads) {
        int n = idx >> 8, k = idx & 255;
        int gate = (n & 7) >> 1;
        int ul = 4 * (n >> 4) + 2 * ((n >> 3) & 1) + (n & 1);
        float v = Wh[k * 1024 + gate * 256 + (int)rank * 64 + ul];
        float h = __half2float(__float2half_rn(v));
        *reinterpret_cast<__half*>(smem_raw + WLO + n * 528 + k * 2) =
            __float2half_rn((v - h) * kScale);
    }

    // ---- W_hi B-fragments, register-resident -------------------------------
    uint32_t wh0[32], wh1[32];
#pragma unroll
    for (int j = 0; j < 2; ++j) {
        int cc = lane >> 2;
        int ul = 4 * w + 2 * j + (cc & 1);
        int gc = (cc >> 1) * 256 + (int)rank * 64 + ul;
#pragma unroll
        for (int kt = 0; kt < 16; ++kt) {
            int k0 = kt * 16 + (lane & 3) * 2;
#pragma unroll
            for (int jj = 0; jj < 2; ++jj) {
                float a = Wh[(k0 + 8 * jj) * 1024 + gc];
                float b = Wh[(k0 + 8 * jj + 1) * 1024 + gc];
                uint32_t v = pack2h(__half2float(__float2half_rn(a)),
                                    __half2float(__float2half_rn(b)));
                if (j == 0) wh0[kt * 2 + jj] = v; else wh1[kt * 2 + jj] = v;
            }
        }
    }

    // ---- per-lane cell constants ------------------------------------------
    float bi[2][4];
#pragma unroll
    for (int j = 0; j < 2; ++j)
#pragma unroll
        for (int g = 0; g < 4; ++g)
            bi[j][g] = bias[g * 256 + (int)rank * 64 + 4 * w + 2 * j + p];
    float cst[2] = {0.f, 0.f};

    // ldmatrix lane address offsets
    // A_hi (x4, m16k16): mats = rows0-7/k-lo, rows8-15/k-lo, rows0-7/k-hi, rows8-15/k-hi
    const uint32_t aoff =
        (uint32_t)(((((lane >> 3) & 1) * 8) + (lane & 7)) * 528 +
                   ((lane >> 4) & 1) * 16);
    // W_lo (x4): mats = tile0/k-lo, tile0/k-hi, tile1/k-lo, tile1/k-hi
    const uint32_t bloff = sbase + WLO +
        (uint32_t)((w * 16 + ((lane >> 4) & 1) * 8 + (lane & 7)) * 528 +
                   ((lane >> 3) & 1) * 16);

    // ---- prologue: stage Wx(t=0) + tokens(t=1) synchronously ---------------
#pragma unroll
    for (int cc = 0; cc < 2; ++cc) {
        int cidx = tid + cc * 512;
        int b = cidx >> 6, c = (cidx & 63) * 4;
        int tok0 = tokens[(bbase + b) * kSeq];
        float4 v = *reinterpret_cast<const float4*>(
            Wx + tok0 * 1024 + (c >> 6) * 256 + (int)rank * 64 + (c & 63));
        *reinterpret_cast<float4*>(smem_raw + WXS + (uint32_t)(b * 1040 + c * 4)) = v;
    }
    if (tid < 16)
        reinterpret_cast<int*>(smem_raw + TKS)[tid] =
            tokens[(bbase + tid) * kSeq + 1];

    __syncthreads();
    cluster_arrive_(); cluster_wait_();

    for (int t = 0; t < kSeq; ++t) {
        const uint32_t q = (uint32_t)(t & 1);

        // ---- cp.async stage: Wx(t+1) via tokens staged last step ----------
        {
            const int* tksP =
                reinterpret_cast<const int*>(smem_raw + TKS) + (int)(q * 16);
            uint32_t wdst = sbase + WXS + (q ^ 1u) * WXS_BUF;
#pragma unroll
            for (int cc = 0; cc < 2; ++cc) {
                int cidx = tid + cc * 512;
                int b = cidx >> 6, c = (cidx & 63) * 4;
                int tok1 = tksP[b];
                cp16_(wdst + (uint32_t)(b * 1040 + c * 4),
                      Wx + tok1 * 1024 + (c >> 6) * 256 + (int)rank * 64 + (c & 63));
            }
            if (tid < 16) {
                int t2 = (t + 2 < kSeq) ? t + 2 : kSeq - 1;
                cp4_(sbase + TKS + ((q ^ 1u) * 16u + (uint32_t)tid) * 4u,
                     tokens + (bbase + tid) * kSeq + t2);
            }
            cp_commit_();
        }

        // ---- gemm: m16 x (2 x n8) x K256, 2-term, reg-double-buffered ------
        float aA0[4] = {0, 0, 0, 0}, aB0[4] = {0, 0, 0, 0};
        float aA1[4] = {0, 0, 0, 0}, aB1[4] = {0, 0, 0, 0};
        const uint32_t ahB = sbase + ABASE + q * A_ARR + aoff;

        uint32_t ah[2][4], bl[2][4];
        ldsm_x4_(ah[0], ahB);
        ldsm_x4_(bl[0], bloff);
#pragma unroll
        for (int kt = 0; kt < 16; ++kt) {
            const int cur = kt & 1, nxt = cur ^ 1;
            if (kt < 15) {                       // prefetch kt+1 fragments
                const uint32_t ko = (uint32_t)((kt + 1) * 32);
                ldsm_x4_(ah[nxt], ahB + ko);
                ldsm_x4_(bl[nxt], bloff + ko);
            }
            mma16816_(aA0, ah[cur], wh0[2 * kt], wh0[2 * kt + 1]);
            mma16816_(aB0, ah[cur], bl[cur][0], bl[cur][1]);
            mma16816_(aA1, ah[cur], wh1[2 * kt], wh1[2 * kt + 1]);
            mma16816_(aB1, ah[cur], bl[cur][2], bl[cur][3]);
        }

        // ---- combine, quad-transpose, cell (wx from staged SMEM) ----------
        const float* wxr = reinterpret_cast<const float*>(smem_raw + WXS + q * WXS_BUF)
                           + r * 260;
        float hv[2];
#pragma unroll
        for (int j = 0; j < 2; ++j) {
            float g[4];
#pragma unroll
            for (int k = 0; k < 4; ++k)
                g[k] = j ? fmaf(aB1[k], kInv, aA1[k]) : fmaf(aB0[k], kInv, aA0[k]);
            quad_transpose(g, m);
            int ul = 4 * w + 2 * j + p;
            float gi = g[0] + wxr[        ul] + bi[j][0];
            float gj = g[1] + wxr[ 64 +   ul] + bi[j][1];
            float gf = g[2] + wxr[128 +   ul] + bi[j][2];
            float go = g[3] + wxr[192 +   ul] + bi[j][3];
            cst[j] = cst[j] * sigf(gf + 1.0f) + sigf(gi) * tanhf_(gj);
            hv[j] = tanhf_(cst[j]) * sigf(go);
        }

        // ---- pack 4 units, broadcast to 4 cluster CTAs (p=0 lanes) --------
        {
            float hp0 = __shfl_xor_sync(0xffffffffu, hv[0], 1);
            float hp1 = __shfl_xor_sync(0xffffffffu, hv[1], 1);
            if (p == 0) {
                uint32_t v0 = pack2h(hv[0], hp0);   // units 4w, 4w+1
                uint32_t v1 = pack2h(hv[1], hp1);   // units 4w+2, 4w+3
                uint32_t off = ABASE + (q ^ 1u) * A_ARR +
                               (uint32_t)(r * 528 + (int)rank * 128 + 8 * w);
#pragma unroll
                for (uint32_t pr = 0; pr < 4; ++pr)
                    st_cluster_v2(mapa_u32(sbase, pr) + off, v0, v1);
            }
        }

        cp_wait0_();          // staged Wx(t+1)/tokens(t+2) resident pre-barrier
        cluster_arrive_();
        cluster_wait_();
    }

    // ---- dense epilogue: out[b,:] = h @ Wd + bd ---------------------------
    {
        float* wds = reinterpret_cast<float*>(smem_raw + WLO);   // 32KB staging
        for (int idx = tid; idx < 256 * 32; idx += kThreads)
            wds[idx] = Wd[(idx >> 5) * 128 + (int)rank * 32 + (idx & 31)];
        __syncthreads();

        int ci = tid & 31, b = tid >> 5;
        int col = (int)rank * 32 + ci;
        const __half* hh = reinterpret_cast<const __half*>(
            smem_raw + ABASE + (uint32_t)(b * 528));
        float acc = bd[col];
#pragma unroll 8
        for (int u = 0; u < 256; ++u)
            acc += __half2float(hh[u]) * wds[u * 32 + ci];
        out[(bbase + b) * 128 + col] = acc;
    }
    cluster_arrive_(); cluster_wait_();
}

extern "C" void kernel_launch(void* const* d_in, const int* in_sizes, int n_in,
                              void* d_out, int out_size) {
    (void)in_sizes; (void)n_in; (void)out_size;
    const int*   tokens = (const int*)d_in[0];
    const float* Wx     = (const float*)d_in[1];
    const float* Wh     = (const float*)d_in[2];
    const float* b      = (const float*)d_in[3];
    const float* Wd     = (const float*)d_in[4];
    const float* bd     = (const float*)d_in[5];
    float* out = (float*)d_out;

    cudaFuncSetAttribute(lstm_db_kernel,
                         cudaFuncAttributeMaxDynamicSharedMemorySize,
                         (int)SMEM_BYTES);
    // 32 clusters of 4 CTAs (static __cluster_dims__), 1 CTA/SM.
    lstm_db_kernel<<<128, kThreads, SMEM_BYTES>>>(tokens, Wx, Wh, b, Wd, bd, out);
}